// round 12
// baseline (speedup 1.0000x reference)
#include <cuda_runtime.h>
#include <cuda_fp16.h>
#include <math.h>

#define N_FIELDS 8
#define HIDDEN   128
#define GEO      15
#define APP      32
#define CIN      50
#define N_MAX    524288
#define TILE     128
#define TILES_PER_BLOCK 8
#define PTS_PER_BLOCK   1024

#define H_STRIDE   36    // words/row; 4g+tg bank pattern -> conflict-free
#define WD2_STRIDE 68    // n-major [16][68]; 68%32=4 -> 4g+tg conflict-free
#define WC1_STRIDE 136   // 136%32=8 -> 8tg+g conflict-free

// ---- dynamic smem layout (32-bit word offsets) ----
#define OFF_WD1    0       // 384
#define OFF_BD1    384     // 128
#define OFF_BD2    512     // 16
#define OFF_BC1    528     // 128
#define OFF_BC2    656     // 4
#define OFF_WC2    660     // 512 (float4[128]); byte 2640, 16B aligned
#define OFF_WD2H   1172    // [16][68] = 1088
#define OFF_WC1    2260    // [32][136] = 4352 ; byte 9040, 16B aligned
#define OFF_H      6612    // [128][36] = 4608 ; byte 26448, 16B aligned
#define SMEM_WORDS 11220
#define SMEM_BYTES (SMEM_WORDS * 4)   // 44880 B -> 5 blocks/SM

// ---------------- device scratch ----------------
__device__ int g_counts[N_FIELDS];
__device__ int g_bucket[N_FIELDS][N_MAX];

__global__ void k_assign(const float* __restrict__ pos,
                         const float* __restrict__ cent, int n) {
    int i = blockIdx.x * blockDim.x + threadIdx.x;
    unsigned act = __ballot_sync(0xffffffffu, i < n);
    if (i >= n) return;
    float px = pos[3*i], py = pos[3*i+1], pz = pos[3*i+2];
    int best = 0; float bd = 3.402823e38f;
    #pragma unroll
    for (int c = 0; c < N_FIELDS; c++) {
        float dx = px - __ldg(&cent[3*c+0]);
        float dy = py - __ldg(&cent[3*c+1]);
        float dz = pz - __ldg(&cent[3*c+2]);
        float d = dx*dx + dy*dy + dz*dz;
        if (d < bd) { bd = d; best = c; }
    }
    unsigned peers  = __match_any_sync(act, best);
    int leader = __ffs(peers) - 1;
    int lane   = threadIdx.x & 31;
    int base = 0;
    if (lane == leader) base = atomicAdd(&g_counts[best], __popc(peers));
    base = __shfl_sync(peers, base, leader);
    g_bucket[best][base + __popc(peers & ((1u << lane) - 1u))] = i;
}

// ---- helpers ----
__device__ __forceinline__ unsigned packh2(float lo, float hi) {
    __half2 h = __floats2half2_rn(lo, hi);
    return *(unsigned*)&h;
}
__device__ __forceinline__ void mma_f16(float& c0, float& c1, float& c2, float& c3,
                                        unsigned a0, unsigned a1, unsigned a2, unsigned a3,
                                        unsigned b0, unsigned b1) {
    asm("mma.sync.aligned.m16n8k16.row.col.f32.f16.f16.f32 "
        "{%0,%1,%2,%3},{%4,%5,%6,%7},{%8,%9},{%0,%1,%2,%3};"
        : "+f"(c0), "+f"(c1), "+f"(c2), "+f"(c3)
        : "r"(a0), "r"(a1), "r"(a2), "r"(a3), "r"(b0), "r"(b1));
}

// ---------------- kernel 2 ----------------
__global__ void __launch_bounds__(TILE, 5)
k_field(const float* __restrict__ pos, const float* __restrict__ dir,
        const float* __restrict__ app,
        const float* __restrict__ Wd1, const float* __restrict__ bd1,
        const float* __restrict__ Wd2, const float* __restrict__ bd2,
        const float* __restrict__ Wc1, const float* __restrict__ bc1,
        const float* __restrict__ Wc2, const float* __restrict__ bc2,
        float* __restrict__ out, int tpf)
{
    extern __shared__ float sm[];
    unsigned* smw = (unsigned*)sm;

    int f = blockIdx.x / tpf;
    int t = blockIdx.x - f * tpf;
    int cnt = g_counts[f];
    if (t * PTS_PER_BLOCK >= cnt) return;

    int tid = threadIdx.x;

    // ---- stage weights (once per block) ----
    {
        const float* g = Wd1 + f*3*HIDDEN;
        for (int i = tid; i < 3*HIDDEN; i += TILE) sm[OFF_WD1 + i] = g[i];
    }
    sm[OFF_BD1 + tid] = bd1[f*HIDDEN + tid];
    if (tid < 16) sm[OFF_BD2 + tid] = bd2[f*16 + tid];
    sm[OFF_BC1 + tid] = bc1[f*HIDDEN + tid];
    if (tid < 3) sm[OFF_BC2 + tid] = bc2[f*3 + tid];
    if (tid == 3) sm[OFF_BC2 + 3] = 0.f;
    {   // Wd2 [k=128][n=16] -> n-major half2: [n=16][kp=64], stride 68
        const float* g = Wd2 + f*HIDDEN*16;
        for (int i = tid; i < 16*64; i += TILE) {
            int n = i >> 6, kp = i & 63;
            smw[OFF_WD2H + n*WD2_STRIDE + kp] =
                packh2(g[(2*kp)*16 + n], g[(2*kp+1)*16 + n]);
        }
    }
    {   // Wc1 [k=50][n=128] -> half2 [kp=32][n=128], stride 136 (k padded to 64)
        const float* g = Wc1 + f*CIN*HIDDEN;
        for (int i = tid; i < 32*HIDDEN; i += TILE) {
            int kp = i >> 7, nn = i & 127;
            unsigned w = 0u;
            if (kp < 25)
                w = packh2(g[(2*kp)*HIDDEN + nn], g[(2*kp+1)*HIDDEN + nn]);
            smw[OFF_WC1 + kp*WC1_STRIDE + nn] = w;
        }
    }
    {
        const float* g = Wc2 + f*HIDDEN*3;
        sm[OFF_WC2 + tid*4+0] = g[tid*3+0];
        sm[OFF_WC2 + tid*4+1] = g[tid*3+1];
        sm[OFF_WC2 + tid*4+2] = g[tid*3+2];
        sm[OFF_WC2 + tid*4+3] = 0.f;
    }
    __syncthreads();

    int lane = tid & 31;
    int wid  = tid >> 5;
    int g    = lane >> 2;
    int tg   = lane & 3;
    int wbase = wid * 32;

    const unsigned* H32  = smw + OFF_H;
    const unsigned* WD2w = smw + OFF_WD2H;
    const unsigned* W32  = smw + OFF_WC1;
    const float4*  WC2v  = (const float4*)(sm + OFF_WC2);

    for (int tile = 0; tile < TILES_PER_BLOCK; tile++) {
        int base = t * PTS_PER_BLOCK + tile * TILE;
        if (base >= cnt) break;
        int bi = base + tid;
        bool valid = (bi < cnt);
        int p = g_bucket[f][valid ? bi : (cnt - 1)];

        float px = pos[3*p], py = pos[3*p+1], pz = pos[3*p+2];
        uint4* hrow = (uint4*)(smw + OFF_H + tid*H_STRIDE);

        float cd[2][2][8];   // [mt][nt][cA0..3, cB0..3] — lives across both halves
        #pragma unroll
        for (int mt = 0; mt < 2; mt++)
            #pragma unroll
            for (int nt = 0; nt < 2; nt++)
                #pragma unroll
                for (int q = 0; q < 8; q++) cd[mt][nt][q] = 0.f;

        // ==== two K-halves of the density GEMM, h tile reused in-place ====
        #pragma unroll
        for (int hb = 0; hb < 2; hb++) {
            // ---- L1: h[64*hb .. 64*hb+63] -> H words 0..31 ----
            #pragma unroll
            for (int j = 0; j < 64; j += 8) {
                float hv[8];
                #pragma unroll
                for (int u = 0; u < 8; u++) {
                    int jj = 64*hb + j + u;
                    hv[u] = fmaxf(fmaf(px, sm[OFF_WD1 + 0*HIDDEN + jj],
                                  fmaf(py, sm[OFF_WD1 + 1*HIDDEN + jj],
                                  fmaf(pz, sm[OFF_WD1 + 2*HIDDEN + jj],
                                       sm[OFF_BD1 + jj]))), 0.f);
                }
                hrow[j >> 3] = make_uint4(packh2(hv[0],hv[1]), packh2(hv[2],hv[3]),
                                          packh2(hv[4],hv[5]), packh2(hv[6],hv[7]));
            }
            __syncwarp();

            // ---- per-mt: load A-frags (scalar LDS), then MMA ----
            #pragma unroll
            for (int mt = 0; mt < 2; mt++) {
                int r0 = wbase + 16*mt + g;
                unsigned a1[4][4];
                #pragma unroll
                for (int ks = 0; ks < 4; ks++) {
                    int c = 8*ks + tg;
                    a1[ks][0] = H32[(r0    )*H_STRIDE + c    ];
                    a1[ks][1] = H32[(r0 + 8)*H_STRIDE + c    ];
                    a1[ks][2] = H32[(r0    )*H_STRIDE + c + 4];
                    a1[ks][3] = H32[(r0 + 8)*H_STRIDE + c + 4];
                }
                #pragma unroll
                for (int nt = 0; nt < 2; nt++) {
                    int coln = 8*nt + g;
                    float* c = cd[mt][nt];
                    #pragma unroll
                    for (int ks = 0; ks < 4; ks += 2) {
                        int gk0 = 4*hb + ks, gk1 = gk0 + 1;
                        unsigned b00 = WD2w[coln*WD2_STRIDE + 8*gk0 + tg    ];
                        unsigned b01 = WD2w[coln*WD2_STRIDE + 8*gk0 + tg + 4];
                        unsigned b10 = WD2w[coln*WD2_STRIDE + 8*gk1 + tg    ];
                        unsigned b11 = WD2w[coln*WD2_STRIDE + 8*gk1 + tg + 4];
                        mma_f16(c[0],c[1],c[2],c[3],
                                a1[ks][0],a1[ks][1],a1[ks][2],a1[ks][3], b00,b01);
                        mma_f16(c[4],c[5],c[6],c[7],
                                a1[ks+1][0],a1[ks+1][1],a1[ks+1][2],a1[ks+1][3], b10,b11);
                    }
                }
            }
            __syncwarp();   // before overwriting H (hb=0) / storing d0 (hb=1)
        }

        // ---- store d0 frags into H words 0..15 of own rows ----
        #pragma unroll
        for (int mt = 0; mt < 2; mt++) {
            int r0 = wbase + 16*mt + g;
            #pragma unroll
            for (int nt = 0; nt < 2; nt++) {
                float* c = cd[mt][nt];
                int cb = 8*nt + 2*tg;
                float* rA = sm + OFF_H + (size_t)(r0    )*H_STRIDE + cb;
                float* rB = sm + OFF_H + (size_t)(r0 + 8)*H_STRIDE + cb;
                rA[0] = c[0] + c[4];  rA[1] = c[1] + c[5];
                rB[0] = c[2] + c[6];  rB[1] = c[3] + c[7];
            }
        }
        __syncwarp();

        // ---- readback d0 (own row), density out, build CIN in-place ----
        {
            float d0[16];
            const float4* drow = (const float4*)(sm + OFF_H + (size_t)tid*H_STRIDE);
            #pragma unroll
            for (int q = 0; q < 4; q++) {
                float4 v = drow[q];
                d0[4*q+0] = v.x + sm[OFF_BD2 + 4*q+0];
                d0[4*q+1] = v.y + sm[OFF_BD2 + 4*q+1];
                d0[4*q+2] = v.z + sm[OFF_BD2 + 4*q+2];
                d0[4*q+3] = v.w + sm[OFF_BD2 + 4*q+3];
            }
            if (valid) out[(size_t)4*p] = expf(d0[0]);

            float cv[56];
            cv[0] = dir[3*p]; cv[1] = dir[3*p+1]; cv[2] = dir[3*p+2];
            #pragma unroll
            for (int g2 = 0; g2 < GEO; g2++) cv[3+g2] = d0[1+g2];
            const float4* ap = (const float4*)(app + (size_t)p*APP);
            #pragma unroll
            for (int q = 0; q < APP/4; q++) {
                float4 v = __ldg(&ap[q]);
                cv[18+4*q+0] = v.x; cv[18+4*q+1] = v.y;
                cv[18+4*q+2] = v.z; cv[18+4*q+3] = v.w;
            }
            #pragma unroll
            for (int c = CIN; c < 56; c++) cv[c] = 0.f;
            #pragma unroll
            for (int q = 0; q < 8; q++) {     // words 0..31 (k padded to 64)
                uint4 v;
                v.x = (q < 7) ? packh2(cv[8*q+0], cv[8*q+1]) : 0u;
                v.y = (q < 7) ? packh2(cv[8*q+2], cv[8*q+3]) : 0u;
                v.z = (q < 7) ? packh2(cv[8*q+4], cv[8*q+5]) : 0u;
                v.w = (q < 7) ? packh2(cv[8*q+6], cv[8*q+7]) : 0u;
                hrow[q] = v;
            }
        }
        __syncwarp();

        // ---- color MMA per mt: HC = relu(CIN @ Wc1 + bc1); RGB fused ----
        float acc[4][3];
        #pragma unroll
        for (int q = 0; q < 4; q++) { acc[q][0]=0.f; acc[q][1]=0.f; acc[q][2]=0.f; }

        #pragma unroll
        for (int mt = 0; mt < 2; mt++) {
            int r0 = wbase + 16*mt + g;
            unsigned a[4][4];
            #pragma unroll
            for (int ks = 0; ks < 4; ks++) {
                int c = 8*ks + tg;
                a[ks][0] = H32[(r0    )*H_STRIDE + c    ];
                a[ks][1] = H32[(r0 + 8)*H_STRIDE + c    ];
                a[ks][2] = H32[(r0    )*H_STRIDE + c + 4];
                a[ks][3] = H32[(r0 + 8)*H_STRIDE + c + 4];
            }
            int q0 = 2*mt, q1 = 2*mt + 1;

            #pragma unroll 2
            for (int nb = 0; nb < 16; nb++) {
                int coln = 8*nb + g;
                unsigned b[4][2];
                #pragma unroll
                for (int ks = 0; ks < 4; ks++) {
                    b[ks][0] = W32[(8*ks + tg    )*WC1_STRIDE + coln];
                    b[ks][1] = W32[(8*ks + tg + 4)*WC1_STRIDE + coln];
                }
                int j0 = 8*nb + 2*tg;
                float bj0 = sm[OFF_BC1 + j0], bj1 = sm[OFF_BC1 + j0 + 1];
                float4 w0 = WC2v[j0];
                float4 w1 = WC2v[j0 + 1];

                float cA0=0.f,cA1=0.f,cA2=0.f,cA3=0.f;
                float cB0=0.f,cB1=0.f,cB2=0.f,cB3=0.f;
                mma_f16(cA0,cA1,cA2,cA3, a[0][0],a[0][1],a[0][2],a[0][3], b[0][0],b[0][1]);
                mma_f16(cB0,cB1,cB2,cB3, a[1][0],a[1][1],a[1][2],a[1][3], b[1][0],b[1][1]);
                mma_f16(cA0,cA1,cA2,cA3, a[2][0],a[2][1],a[2][2],a[2][3], b[2][0],b[2][1]);
                mma_f16(cB0,cB1,cB2,cB3, a[3][0],a[3][1],a[3][2],a[3][3], b[3][0],b[3][1]);
                float h00 = fmaxf(cA0 + cB0 + bj0, 0.f);
                float h01 = fmaxf(cA1 + cB1 + bj1, 0.f);
                float h10 = fmaxf(cA2 + cB2 + bj0, 0.f);
                float h11 = fmaxf(cA3 + cB3 + bj1, 0.f);
                acc[q0][0] = fmaf(h00, w0.x, fmaf(h01, w1.x, acc[q0][0]));
                acc[q0][1] = fmaf(h00, w0.y, fmaf(h01, w1.y, acc[q0][1]));
                acc[q0][2] = fmaf(h00, w0.z, fmaf(h01, w1.z, acc[q0][2]));
                acc[q1][0] = fmaf(h10, w0.x, fmaf(h11, w1.x, acc[q1][0]));
                acc[q1][1] = fmaf(h10, w0.y, fmaf(h11, w1.y, acc[q1][1]));
                acc[q1][2] = fmaf(h10, w0.z, fmaf(h11, w1.z, acc[q1][2]));
            }
        }

        #pragma unroll
        for (int q = 0; q < 4; q++)
            #pragma unroll
            for (int c = 0; c < 3; c++) {
                float v = acc[q][c];
                v += __shfl_xor_sync(0xffffffffu, v, 1);
                v += __shfl_xor_sync(0xffffffffu, v, 2);
                acc[q][c] = v;
            }

        {
            int row = wbase + g + 8*tg;
            int bi2 = base + row;
            if (bi2 < cnt) {
                int pp = g_bucket[f][bi2];
                float r0 = acc[tg][0] + sm[OFF_BC2 + 0];
                float r1 = acc[tg][1] + sm[OFF_BC2 + 1];
                float r2 = acc[tg][2] + sm[OFF_BC2 + 2];
                out[(size_t)4*pp + 1] = 1.f / (1.f + expf(-r0));
                out[(size_t)4*pp + 2] = 1.f / (1.f + expf(-r1));
                out[(size_t)4*pp + 3] = 1.f / (1.f + expf(-r2));
            }
        }
        __syncwarp();   // protect H reuse next tile
    }
}

// ---------------- launch ----------------
extern "C" void kernel_launch(void* const* d_in, const int* in_sizes, int n_in,
                              void* d_out, int out_size) {
    const float* positions  = (const float*)d_in[0];
    const float* directions = (const float*)d_in[1];
    const float* appearance = (const float*)d_in[2];
    const float* centroids  = (const float*)d_in[3];
    const float* Wd1 = (const float*)d_in[4];
    const float* bd1 = (const float*)d_in[5];
    const float* Wd2 = (const float*)d_in[6];
    const float* bd2 = (const float*)d_in[7];
    const float* Wc1 = (const float*)d_in[8];
    const float* bc1 = (const float*)d_in[9];
    const float* Wc2 = (const float*)d_in[10];
    const float* bc2 = (const float*)d_in[11];
    float* out = (float*)d_out;

    int n = in_sizes[0] / 3;
    if (n > N_MAX) n = N_MAX;
    int tpf = (n + PTS_PER_BLOCK - 1) / PTS_PER_BLOCK;

    cudaFuncSetAttribute(k_field, cudaFuncAttributeMaxDynamicSharedMemorySize,
                         SMEM_BYTES);

    void* cptr = nullptr;
    cudaGetSymbolAddress(&cptr, g_counts);
    cudaMemsetAsync(cptr, 0, N_FIELDS * sizeof(int));

    k_assign<<<(n + 255) / 256, 256>>>(positions, centroids, n);
    k_field<<<N_FIELDS * tpf, TILE, SMEM_BYTES>>>(positions, directions, appearance,
                                                  Wd1, bd1, Wd2, bd2, Wc1, bc1,
                                                  Wc2, bc2, out, tpf);
}

// round 13
// speedup vs baseline: 1.4818x; 1.4818x over previous
#include <cuda_runtime.h>
#include <cuda_fp16.h>
#include <math.h>

#define N_FIELDS 8
#define HIDDEN   128
#define GEO      15
#define APP      32
#define CIN      50
#define N_MAX    524288
#define TILE     128
#define TILES_PER_BLOCK 8
#define PTS_PER_BLOCK   1024

#define H_STRIDE   36    // words/row; 4g+tg bank pattern -> conflict-free
#define WD2_STRIDE 24    // k-major [kp=64][n=16]; 24tg+coln -> conflict-free
#define WC1_STRIDE 136   // 136%32=8 -> 8tg+g conflict-free
#define P_STRIDE   4     // pos tile [128][4] half2 words; 4g+tg
#define WB1_STRIDE 4     // Wd1 n-major [128][4] half2 words

// ---- dynamic smem layout (32-bit word offsets) ----
#define OFF_BD1    0       // 128
#define OFF_BD2    128     // 16
#define OFF_BC1    144     // 128
#define OFF_BC2    272     // 4
#define OFF_WC2    276     // 512 (float4[128]); byte 1104, 16B aligned
#define OFF_WD2H   788     // [64][24] = 1536
#define OFF_WC1    2324    // [32][136] = 4352 ; byte 9296, 16B aligned
#define OFF_P      6676    // [128][4] = 512
#define OFF_WB1    7188    // [128][4] = 512
#define OFF_H      7700    // [128][36] = 4608 ; byte 30800, 16B aligned
#define SMEM_WORDS 12308
#define SMEM_BYTES (SMEM_WORDS * 4)   // 49232 B -> 4 blocks/SM

// ---------------- device scratch ----------------
__device__ int g_counts[N_FIELDS];
__device__ int g_bucket[N_FIELDS][N_MAX];

__global__ void k_assign(const float* __restrict__ pos,
                         const float* __restrict__ cent, int n) {
    int i = blockIdx.x * blockDim.x + threadIdx.x;
    unsigned act = __ballot_sync(0xffffffffu, i < n);
    if (i >= n) return;
    float px = pos[3*i], py = pos[3*i+1], pz = pos[3*i+2];
    int best = 0; float bd = 3.402823e38f;
    #pragma unroll
    for (int c = 0; c < N_FIELDS; c++) {
        float dx = px - __ldg(&cent[3*c+0]);
        float dy = py - __ldg(&cent[3*c+1]);
        float dz = pz - __ldg(&cent[3*c+2]);
        float d = dx*dx + dy*dy + dz*dz;
        if (d < bd) { bd = d; best = c; }
    }
    unsigned peers  = __match_any_sync(act, best);
    int leader = __ffs(peers) - 1;
    int lane   = threadIdx.x & 31;
    int base = 0;
    if (lane == leader) base = atomicAdd(&g_counts[best], __popc(peers));
    base = __shfl_sync(peers, base, leader);
    g_bucket[best][base + __popc(peers & ((1u << lane) - 1u))] = i;
}

// ---- helpers ----
__device__ __forceinline__ unsigned packh2(float lo, float hi) {
    __half2 h = __floats2half2_rn(lo, hi);
    return *(unsigned*)&h;
}
__device__ __forceinline__ unsigned hmax2z(unsigned w) {
    __half2 h = *(__half2*)&w;
    h = __hmax2(h, __float2half2_rn(0.f));
    return *(unsigned*)&h;
}
__device__ __forceinline__ void mma_f16(float& c0, float& c1, float& c2, float& c3,
                                        unsigned a0, unsigned a1, unsigned a2, unsigned a3,
                                        unsigned b0, unsigned b1) {
    asm("mma.sync.aligned.m16n8k16.row.col.f32.f16.f16.f32 "
        "{%0,%1,%2,%3},{%4,%5,%6,%7},{%8,%9},{%0,%1,%2,%3};"
        : "+f"(c0), "+f"(c1), "+f"(c2), "+f"(c3)
        : "r"(a0), "r"(a1), "r"(a2), "r"(a3), "r"(b0), "r"(b1));
}
__device__ __forceinline__ void mma_f16_k8(float& c0, float& c1, float& c2, float& c3,
                                           unsigned a0, unsigned a1, unsigned b0) {
    asm("mma.sync.aligned.m16n8k8.row.col.f32.f16.f16.f32 "
        "{%0,%1,%2,%3},{%4,%5},{%6},{%0,%1,%2,%3};"
        : "+f"(c0), "+f"(c1), "+f"(c2), "+f"(c3)
        : "r"(a0), "r"(a1), "r"(b0));
}

// ---------------- kernel 2 ----------------
__global__ void __launch_bounds__(TILE, 4)
k_field(const float* __restrict__ pos, const float* __restrict__ dir,
        const float* __restrict__ app,
        const float* __restrict__ Wd1, const float* __restrict__ bd1,
        const float* __restrict__ Wd2, const float* __restrict__ bd2,
        const float* __restrict__ Wc1, const float* __restrict__ bc1,
        const float* __restrict__ Wc2, const float* __restrict__ bc2,
        float* __restrict__ out, int tpf)
{
    extern __shared__ float sm[];
    unsigned* smw = (unsigned*)sm;

    int f = blockIdx.x / tpf;
    int t = blockIdx.x - f * tpf;
    int cnt = g_counts[f];
    if (t * PTS_PER_BLOCK >= cnt) return;

    int tid = threadIdx.x;

    // ---- stage weights (once per block) ----
    sm[OFF_BD1 + tid] = bd1[f*HIDDEN + tid];
    if (tid < 16) sm[OFF_BD2 + tid] = bd2[f*16 + tid];
    sm[OFF_BC1 + tid] = bc1[f*HIDDEN + tid];
    if (tid < 3) sm[OFF_BC2 + tid] = bc2[f*3 + tid];
    if (tid == 3) sm[OFF_BC2 + 3] = 0.f;
    {   // Wd1 [3][128] -> n-major half2 [n=128][4]: (w0x,w0y),(w0z,0),0,0
        const float* g = Wd1 + f*3*HIDDEN;
        smw[OFF_WB1 + tid*WB1_STRIDE + 0] = packh2(g[0*HIDDEN + tid], g[1*HIDDEN + tid]);
        smw[OFF_WB1 + tid*WB1_STRIDE + 1] = packh2(g[2*HIDDEN + tid], 0.f);
        smw[OFF_WB1 + tid*WB1_STRIDE + 2] = 0u;
        smw[OFF_WB1 + tid*WB1_STRIDE + 3] = 0u;
        // P tile pad words (k 4..7 of pos) zeroed once
        smw[OFF_P + tid*P_STRIDE + 2] = 0u;
        smw[OFF_P + tid*P_STRIDE + 3] = 0u;
    }
    {   // Wd2 [k=128][n=16] -> half2 [kp=64][n=16], stride 24 (R10 layout)
        const float* g = Wd2 + f*HIDDEN*16;
        for (int i = tid; i < 64*16; i += TILE) {
            int kp = i >> 4, nn = i & 15;
            smw[OFF_WD2H + kp*WD2_STRIDE + nn] =
                packh2(g[(2*kp)*16 + nn], g[(2*kp+1)*16 + nn]);
        }
    }
    {   // Wc1 [k=50][n=128] -> half2 [kp=32][n=128], stride 136 (R10 layout)
        const float* g = Wc1 + f*CIN*HIDDEN;
        for (int i = tid; i < 32*HIDDEN; i += TILE) {
            int kp = i >> 7, nn = i & 127;
            unsigned w = 0u;
            if (kp < 25)
                w = packh2(g[(2*kp)*HIDDEN + nn], g[(2*kp+1)*HIDDEN + nn]);
            smw[OFF_WC1 + kp*WC1_STRIDE + nn] = w;
        }
    }
    {
        const float* g = Wc2 + f*HIDDEN*3;
        sm[OFF_WC2 + tid*4+0] = g[tid*3+0];
        sm[OFF_WC2 + tid*4+1] = g[tid*3+1];
        sm[OFF_WC2 + tid*4+2] = g[tid*3+2];
        sm[OFF_WC2 + tid*4+3] = 0.f;
    }
    __syncthreads();

    int lane = tid & 31;
    int wid  = tid >> 5;
    int g    = lane >> 2;
    int tg   = lane & 3;
    int wbase = wid * 32;

    const unsigned* H32  = smw + OFF_H;
    const unsigned* WD2w = smw + OFF_WD2H;
    const unsigned* W32  = smw + OFF_WC1;
    const unsigned* P32  = smw + OFF_P;
    const unsigned* WB1w = smw + OFF_WB1;
    const float4*  WC2v  = (const float4*)(sm + OFF_WC2);

    for (int tile = 0; tile < TILES_PER_BLOCK; tile++) {
        int base = t * PTS_PER_BLOCK + tile * TILE;
        if (base >= cnt) break;
        int bi = base + tid;
        bool valid = (bi < cnt);
        int p = g_bucket[f][valid ? bi : (cnt - 1)];

        float px = pos[3*p], py = pos[3*p+1], pz = pos[3*p+2];
        uint4* hrow = (uint4*)(smw + OFF_H + tid*H_STRIDE);

        // ---- stage this tile's pos rows (words 0,1; pads stay zero) ----
        smw[OFF_P + tid*P_STRIDE + 0] = packh2(px, py);
        smw[OFF_P + tid*P_STRIDE + 1] = packh2(pz, 0.f);
        __syncwarp();

        // pos A-frags: loaded once, reused by all 32 L1 MMAs
        unsigned pa[2][2];
        #pragma unroll
        for (int mt = 0; mt < 2; mt++) {
            int r0 = wbase + 16*mt + g;
            pa[mt][0] = P32[(r0    )*P_STRIDE + tg];
            pa[mt][1] = P32[(r0 + 8)*P_STRIDE + tg];
        }

        float cd[2][2][8];   // [mt][nt][cA0..3, cB0..3] for d0 GEMM
        #pragma unroll
        for (int mt = 0; mt < 2; mt++)
            #pragma unroll
            for (int nt = 0; nt < 2; nt++)
                #pragma unroll
                for (int q = 0; q < 8; q++) cd[mt][nt][q] = 0.f;

        // ==== two K-halves: L1 via MMA -> H words 0..31 -> d0 MMA ====
        #pragma unroll
        for (int hb = 0; hb < 2; hb++) {
            // ---- L1 MMA: h[64*hb + 0..63] = relu(pos @ Wd1 + bd1) ----
            #pragma unroll
            for (int nb8 = 0; nb8 < 8; nb8++) {
                int jn = 64*hb + 8*nb8;
                unsigned b0 = WB1w[(jn + g)*WB1_STRIDE + tg];
                float2 bj = *(const float2*)&sm[OFF_BD1 + jn + 2*tg];
                #pragma unroll
                for (int mt = 0; mt < 2; mt++) {
                    float c0 = bj.x, c1 = bj.y, c2 = bj.x, c3 = bj.y;
                    mma_f16_k8(c0, c1, c2, c3, pa[mt][0], pa[mt][1], b0);
                    unsigned w0 = hmax2z(packh2(c0, c1));   // row g
                    unsigned w1 = hmax2z(packh2(c2, c3));   // row g+8
                    int r0 = wbase + 16*mt + g;
                    smw[OFF_H + (r0    )*H_STRIDE + 4*nb8 + tg] = w0;
                    smw[OFF_H + (r0 + 8)*H_STRIDE + 4*nb8 + tg] = w1;
                }
            }
            __syncwarp();

            // ---- d0 MMA for this half (R10 structure) ----
            unsigned a1[2][4][4];
            #pragma unroll
            for (int mt = 0; mt < 2; mt++) {
                int r0 = wbase + 16*mt + g;
                #pragma unroll
                for (int ks = 0; ks < 4; ks++) {
                    int c = 8*ks + tg;
                    a1[mt][ks][0] = H32[(r0    )*H_STRIDE + c    ];
                    a1[mt][ks][1] = H32[(r0 + 8)*H_STRIDE + c    ];
                    a1[mt][ks][2] = H32[(r0    )*H_STRIDE + c + 4];
                    a1[mt][ks][3] = H32[(r0 + 8)*H_STRIDE + c + 4];
                }
            }
            #pragma unroll
            for (int nt = 0; nt < 2; nt++) {
                int coln = 8*nt + g;
                #pragma unroll
                for (int mt = 0; mt < 2; mt++) {
                    float* c = cd[mt][nt];
                    #pragma unroll
                    for (int ks = 0; ks < 4; ks += 2) {
                        int gk0 = 4*hb + ks, gk1 = gk0 + 1;
                        unsigned b00 = WD2w[(8*gk0 + tg    )*WD2_STRIDE + coln];
                        unsigned b01 = WD2w[(8*gk0 + tg + 4)*WD2_STRIDE + coln];
                        unsigned b10 = WD2w[(8*gk1 + tg    )*WD2_STRIDE + coln];
                        unsigned b11 = WD2w[(8*gk1 + tg + 4)*WD2_STRIDE + coln];
                        mma_f16(c[0],c[1],c[2],c[3],
                                a1[mt][ks][0],a1[mt][ks][1],a1[mt][ks][2],a1[mt][ks][3], b00,b01);
                        mma_f16(c[4],c[5],c[6],c[7],
                                a1[mt][ks+1][0],a1[mt][ks+1][1],a1[mt][ks+1][2],a1[mt][ks+1][3], b10,b11);
                    }
                }
            }
            __syncwarp();   // before overwriting H (hb=0) / storing d0 (hb=1)
        }

        // ---- store d0 frags into H words 0..15 of own rows ----
        #pragma unroll
        for (int mt = 0; mt < 2; mt++) {
            int r0 = wbase + 16*mt + g;
            #pragma unroll
            for (int nt = 0; nt < 2; nt++) {
                float* c = cd[mt][nt];
                int cb = 8*nt + 2*tg;
                float* rA = sm + OFF_H + (size_t)(r0    )*H_STRIDE + cb;
                float* rB = sm + OFF_H + (size_t)(r0 + 8)*H_STRIDE + cb;
                rA[0] = c[0] + c[4];  rA[1] = c[1] + c[5];
                rB[0] = c[2] + c[6];  rB[1] = c[3] + c[7];
            }
        }
        __syncwarp();

        // ---- readback d0 (own row), density out, build CIN in-place ----
        {
            float d0[16];
            const float4* drow = (const float4*)(sm + OFF_H + (size_t)tid*H_STRIDE);
            #pragma unroll
            for (int q = 0; q < 4; q++) {
                float4 v = drow[q];
                d0[4*q+0] = v.x + sm[OFF_BD2 + 4*q+0];
                d0[4*q+1] = v.y + sm[OFF_BD2 + 4*q+1];
                d0[4*q+2] = v.z + sm[OFF_BD2 + 4*q+2];
                d0[4*q+3] = v.w + sm[OFF_BD2 + 4*q+3];
            }
            if (valid) out[(size_t)4*p] = expf(d0[0]);

            float cv[56];
            cv[0] = dir[3*p]; cv[1] = dir[3*p+1]; cv[2] = dir[3*p+2];
            #pragma unroll
            for (int g2 = 0; g2 < GEO; g2++) cv[3+g2] = d0[1+g2];
            const float4* ap = (const float4*)(app + (size_t)p*APP);
            #pragma unroll
            for (int q = 0; q < APP/4; q++) {
                float4 v = __ldg(&ap[q]);
                cv[18+4*q+0] = v.x; cv[18+4*q+1] = v.y;
                cv[18+4*q+2] = v.z; cv[18+4*q+3] = v.w;
            }
            #pragma unroll
            for (int c = CIN; c < 56; c++) cv[c] = 0.f;
            #pragma unroll
            for (int q = 0; q < 8; q++) {     // words 0..31 (k padded to 64)
                uint4 v;
                v.x = (q < 7) ? packh2(cv[8*q+0], cv[8*q+1]) : 0u;
                v.y = (q < 7) ? packh2(cv[8*q+2], cv[8*q+3]) : 0u;
                v.z = (q < 7) ? packh2(cv[8*q+4], cv[8*q+5]) : 0u;
                v.w = (q < 7) ? packh2(cv[8*q+6], cv[8*q+7]) : 0u;
                hrow[q] = v;
            }
        }
        __syncwarp();

        // ---- color MMA (R10 verbatim): HC = relu(CIN@Wc1+bc1); RGB fused ----
        unsigned a[2][4][4];
        #pragma unroll
        for (int mt = 0; mt < 2; mt++) {
            int r0 = wbase + 16*mt + g;
            #pragma unroll
            for (int ks = 0; ks < 4; ks++) {
                int c = 8*ks + tg;
                a[mt][ks][0] = H32[(r0    )*H_STRIDE + c    ];
                a[mt][ks][1] = H32[(r0 + 8)*H_STRIDE + c    ];
                a[mt][ks][2] = H32[(r0    )*H_STRIDE + c + 4];
                a[mt][ks][3] = H32[(r0 + 8)*H_STRIDE + c + 4];
            }
        }

        float acc[4][3];
        #pragma unroll
        for (int q = 0; q < 4; q++) { acc[q][0]=0.f; acc[q][1]=0.f; acc[q][2]=0.f; }

        #pragma unroll 2
        for (int nb = 0; nb < 16; nb++) {
            int coln = 8*nb + g;
            unsigned b[4][2];
            #pragma unroll
            for (int ks = 0; ks < 4; ks++) {
                b[ks][0] = W32[(8*ks + tg    )*WC1_STRIDE + coln];
                b[ks][1] = W32[(8*ks + tg + 4)*WC1_STRIDE + coln];
            }
            int j0 = 8*nb + 2*tg;
            float bj0 = sm[OFF_BC1 + j0], bj1 = sm[OFF_BC1 + j0 + 1];
            float4 w0 = WC2v[j0];
            float4 w1 = WC2v[j0 + 1];

            #pragma unroll
            for (int mt = 0; mt < 2; mt++) {
                float cA0=0.f,cA1=0.f,cA2=0.f,cA3=0.f;
                float cB0=0.f,cB1=0.f,cB2=0.f,cB3=0.f;
                mma_f16(cA0,cA1,cA2,cA3, a[mt][0][0],a[mt][0][1],a[mt][0][2],a[mt][0][3], b[0][0],b[0][1]);
                mma_f16(cB0,cB1,cB2,cB3, a[mt][1][0],a[mt][1][1],a[mt][1][2],a[mt][1][3], b[1][0],b[1][1]);
                mma_f16(cA0,cA1,cA2,cA3, a[mt][2][0],a[mt][2][1],a[mt][2][2],a[mt][2][3], b[2][0],b[2][1]);
                mma_f16(cB0,cB1,cB2,cB3, a[mt][3][0],a[mt][3][1],a[mt][3][2],a[mt][3][3], b[3][0],b[3][1]);
                float h00 = fmaxf(cA0 + cB0 + bj0, 0.f);
                float h01 = fmaxf(cA1 + cB1 + bj1, 0.f);
                float h10 = fmaxf(cA2 + cB2 + bj0, 0.f);
                float h11 = fmaxf(cA3 + cB3 + bj1, 0.f);
                int q0 = 2*mt, q1 = 2*mt + 1;
                acc[q0][0] = fmaf(h00, w0.x, fmaf(h01, w1.x, acc[q0][0]));
                acc[q0][1] = fmaf(h00, w0.y, fmaf(h01, w1.y, acc[q0][1]));
                acc[q0][2] = fmaf(h00, w0.z, fmaf(h01, w1.z, acc[q0][2]));
                acc[q1][0] = fmaf(h10, w0.x, fmaf(h11, w1.x, acc[q1][0]));
                acc[q1][1] = fmaf(h10, w0.y, fmaf(h11, w1.y, acc[q1][1]));
                acc[q1][2] = fmaf(h10, w0.z, fmaf(h11, w1.z, acc[q1][2]));
            }
        }

        #pragma unroll
        for (int q = 0; q < 4; q++)
            #pragma unroll
            for (int c = 0; c < 3; c++) {
                float v = acc[q][c];
                v += __shfl_xor_sync(0xffffffffu, v, 1);
                v += __shfl_xor_sync(0xffffffffu, v, 2);
                acc[q][c] = v;
            }

        {
            int row = wbase + g + 8*tg;
            int bi2 = base + row;
            if (bi2 < cnt) {
                int pp = g_bucket[f][bi2];
                float r0 = acc[tg][0] + sm[OFF_BC2 + 0];
                float r1 = acc[tg][1] + sm[OFF_BC2 + 1];
                float r2 = acc[tg][2] + sm[OFF_BC2 + 2];
                out[(size_t)4*pp + 1] = 1.f / (1.f + expf(-r0));
                out[(size_t)4*pp + 2] = 1.f / (1.f + expf(-r1));
                out[(size_t)4*pp + 3] = 1.f / (1.f + expf(-r2));
            }
        }
        __syncwarp();   // protect H/P reuse next tile
    }
}

// ---------------- launch ----------------
extern "C" void kernel_launch(void* const* d_in, const int* in_sizes, int n_in,
                              void* d_out, int out_size) {
    const float* positions  = (const float*)d_in[0];
    const float* directions = (const float*)d_in[1];
    const float* appearance = (const float*)d_in[2];
    const float* centroids  = (const float*)d_in[3];
    const float* Wd1 = (const float*)d_in[4];
    const float* bd1 = (const float*)d_in[5];
    const float* Wd2 = (const float*)d_in[6];
    const float* bd2 = (const float*)d_in[7];
    const float* Wc1 = (const float*)d_in[8];
    const float* bc1 = (const float*)d_in[9];
    const float* Wc2 = (const float*)d_in[10];
    const float* bc2 = (const float*)d_in[11];
    float* out = (float*)d_out;

    int n = in_sizes[0] / 3;
    if (n > N_MAX) n = N_MAX;
    int tpf = (n + PTS_PER_BLOCK - 1) / PTS_PER_BLOCK;

    cudaFuncSetAttribute(k_field, cudaFuncAttributeMaxDynamicSharedMemorySize,
                         SMEM_BYTES);

    void* cptr = nullptr;
    cudaGetSymbolAddress(&cptr, g_counts);
    cudaMemsetAsync(cptr, 0, N_FIELDS * sizeof(int));

    k_assign<<<(n + 255) / 256, 256>>>(positions, centroids, n);
    k_field<<<N_FIELDS * tpf, TILE, SMEM_BYTES>>>(positions, directions, appearance,
                                                  Wd1, bd1, Wd2, bd2, Wc1, bc1,
                                                  Wc2, bc2, out, tpf);
}

// round 14
// speedup vs baseline: 1.5648x; 1.0561x over previous
#include <cuda_runtime.h>
#include <cuda_fp16.h>
#include <math.h>

#define N_FIELDS 8
#define HIDDEN   128
#define GEO      15
#define APP      32
#define CIN      50
#define N_MAX    524288
#define TILE     128
#define TILES_PER_BLOCK 8
#define PTS_PER_BLOCK   1024

#define H_STRIDE   36    // words/row; CIN + d0 scratch
#define WD2_STRIDE 24    // k-major [kp=64][n=16]; 24tg+coln -> conflict-free
#define WC1_STRIDE 136   // 136%32=8 -> conflict-free
#define P_STRIDE   4     // pos tile [128][4] half2 words; 4g+tg
#define WB1_STRIDE 4     // Wd1 n-major [128][4] half2 words

// ---- dynamic smem layout (32-bit word offsets) ----
#define OFF_BD1    0       // 128
#define OFF_BD2    128     // 16
#define OFF_BC1    144     // 128
#define OFF_BC2    272     // 4
#define OFF_WC2    276     // 512 (float4[128]); byte 1104, 16B aligned
#define OFF_WD2H   788     // [64][24] = 1536
#define OFF_WC1    2324    // [32][136] = 4352 ; byte 9296, 16B aligned
#define OFF_P      6676    // [128][4] = 512
#define OFF_WB1    7188    // [128][4] = 512
#define OFF_H      7700    // [128][36] = 4608 ; byte 30800, 16B aligned
#define SMEM_WORDS 12308
#define SMEM_BYTES (SMEM_WORDS * 4)   // 49232 B -> 4 blocks/SM

// ---------------- device scratch ----------------
__device__ int g_counts[N_FIELDS];
__device__ int g_bucket[N_FIELDS][N_MAX];

__global__ void k_assign(const float* __restrict__ pos,
                         const float* __restrict__ cent, int n) {
    int i = blockIdx.x * blockDim.x + threadIdx.x;
    unsigned act = __ballot_sync(0xffffffffu, i < n);
    if (i >= n) return;
    float px = pos[3*i], py = pos[3*i+1], pz = pos[3*i+2];
    int best = 0; float bd = 3.402823e38f;
    #pragma unroll
    for (int c = 0; c < N_FIELDS; c++) {
        float dx = px - __ldg(&cent[3*c+0]);
        float dy = py - __ldg(&cent[3*c+1]);
        float dz = pz - __ldg(&cent[3*c+2]);
        float d = dx*dx + dy*dy + dz*dz;
        if (d < bd) { bd = d; best = c; }
    }
    unsigned peers  = __match_any_sync(act, best);
    int leader = __ffs(peers) - 1;
    int lane   = threadIdx.x & 31;
    int base = 0;
    if (lane == leader) base = atomicAdd(&g_counts[best], __popc(peers));
    base = __shfl_sync(peers, base, leader);
    g_bucket[best][base + __popc(peers & ((1u << lane) - 1u))] = i;
}

// ---- helpers ----
__device__ __forceinline__ unsigned packh2(float lo, float hi) {
    __half2 h = __floats2half2_rn(lo, hi);
    return *(unsigned*)&h;
}
__device__ __forceinline__ unsigned hmax2z(unsigned w) {
    __half2 h = *(__half2*)&w;
    h = __hmax2(h, __float2half2_rn(0.f));
    return *(unsigned*)&h;
}
__device__ __forceinline__ void mma_f16(float& c0, float& c1, float& c2, float& c3,
                                        unsigned a0, unsigned a1, unsigned a2, unsigned a3,
                                        unsigned b0, unsigned b1) {
    asm("mma.sync.aligned.m16n8k16.row.col.f32.f16.f16.f32 "
        "{%0,%1,%2,%3},{%4,%5,%6,%7},{%8,%9},{%0,%1,%2,%3};"
        : "+f"(c0), "+f"(c1), "+f"(c2), "+f"(c3)
        : "r"(a0), "r"(a1), "r"(a2), "r"(a3), "r"(b0), "r"(b1));
}
__device__ __forceinline__ void mma_f16_k8(float& c0, float& c1, float& c2, float& c3,
                                           unsigned a0, unsigned a1, unsigned b0) {
    asm("mma.sync.aligned.m16n8k8.row.col.f32.f16.f16.f32 "
        "{%0,%1,%2,%3},{%4,%5},{%6},{%0,%1,%2,%3};"
        : "+f"(c0), "+f"(c1), "+f"(c2), "+f"(c3)
        : "r"(a0), "r"(a1), "r"(b0));
}

// ---------------- kernel 2 ----------------
__global__ void __launch_bounds__(TILE, 4)
k_field(const float* __restrict__ pos, const float* __restrict__ dir,
        const float* __restrict__ app,
        const float* __restrict__ Wd1, const float* __restrict__ bd1,
        const float* __restrict__ Wd2, const float* __restrict__ bd2,
        const float* __restrict__ Wc1, const float* __restrict__ bc1,
        const float* __restrict__ Wc2, const float* __restrict__ bc2,
        float* __restrict__ out, int tpf)
{
    extern __shared__ float sm[];
    unsigned* smw = (unsigned*)sm;

    int f = blockIdx.x / tpf;
    int t = blockIdx.x - f * tpf;
    int cnt = g_counts[f];
    if (t * PTS_PER_BLOCK >= cnt) return;

    int tid = threadIdx.x;

    // ---- stage weights (once per block) ----
    sm[OFF_BD1 + tid] = bd1[f*HIDDEN + tid];
    if (tid < 16) sm[OFF_BD2 + tid] = bd2[f*16 + tid];
    sm[OFF_BC1 + tid] = bc1[f*HIDDEN + tid];
    if (tid < 3) sm[OFF_BC2 + tid] = bc2[f*3 + tid];
    if (tid == 3) sm[OFF_BC2 + 3] = 0.f;
    {   // Wd1 [3][128] -> n-major half2 [n=128][4]: (w0x,w0y),(w0z,0),0,0
        const float* g = Wd1 + f*3*HIDDEN;
        smw[OFF_WB1 + tid*WB1_STRIDE + 0] = packh2(g[0*HIDDEN + tid], g[1*HIDDEN + tid]);
        smw[OFF_WB1 + tid*WB1_STRIDE + 1] = packh2(g[2*HIDDEN + tid], 0.f);
        smw[OFF_WB1 + tid*WB1_STRIDE + 2] = 0u;
        smw[OFF_WB1 + tid*WB1_STRIDE + 3] = 0u;
        // P tile pad words (k 4..7 of pos) zeroed once
        smw[OFF_P + tid*P_STRIDE + 2] = 0u;
        smw[OFF_P + tid*P_STRIDE + 3] = 0u;
    }
    {   // Wd2 [k=128][n=16] -> half2 [kp=64][n=16], stride 24
        const float* g = Wd2 + f*HIDDEN*16;
        for (int i = tid; i < 64*16; i += TILE) {
            int kp = i >> 4, nn = i & 15;
            smw[OFF_WD2H + kp*WD2_STRIDE + nn] =
                packh2(g[(2*kp)*16 + nn], g[(2*kp+1)*16 + nn]);
        }
    }
    {   // Wc1 [k=50][n=128] -> half2 [kp=32][n=128], stride 136
        const float* g = Wc1 + f*CIN*HIDDEN;
        for (int i = tid; i < 32*HIDDEN; i += TILE) {
            int kp = i >> 7, nn = i & 127;
            unsigned w = 0u;
            if (kp < 25)
                w = packh2(g[(2*kp)*HIDDEN + nn], g[(2*kp+1)*HIDDEN + nn]);
            smw[OFF_WC1 + kp*WC1_STRIDE + nn] = w;
        }
    }
    {
        const float* g = Wc2 + f*HIDDEN*3;
        sm[OFF_WC2 + tid*4+0] = g[tid*3+0];
        sm[OFF_WC2 + tid*4+1] = g[tid*3+1];
        sm[OFF_WC2 + tid*4+2] = g[tid*3+2];
        sm[OFF_WC2 + tid*4+3] = 0.f;
    }
    __syncthreads();

    int lane = tid & 31;
    int wid  = tid >> 5;
    int g    = lane >> 2;
    int tg   = lane & 3;
    int wbase = wid * 32;

    const unsigned* H32  = smw + OFF_H;
    const unsigned* WD2w = smw + OFF_WD2H;
    const unsigned* W32  = smw + OFF_WC1;
    const unsigned* P32  = smw + OFF_P;
    const unsigned* WB1w = smw + OFF_WB1;
    const float4*  WC2v  = (const float4*)(sm + OFF_WC2);

    for (int tile = 0; tile < TILES_PER_BLOCK; tile++) {
        int base = t * PTS_PER_BLOCK + tile * TILE;
        if (base >= cnt) break;
        int bi = base + tid;
        bool valid = (bi < cnt);
        int p = g_bucket[f][valid ? bi : (cnt - 1)];

        float px = pos[3*p], py = pos[3*p+1], pz = pos[3*p+2];
        uint4* hrow = (uint4*)(smw + OFF_H + tid*H_STRIDE);

        // ---- stage this tile's pos rows (words 0,1; pads stay zero) ----
        smw[OFF_P + tid*P_STRIDE + 0] = packh2(px, py);
        smw[OFF_P + tid*P_STRIDE + 1] = packh2(pz, 0.f);
        __syncwarp();

        // pos A-frags: loaded once, reused by all 32 L1 MMAs
        unsigned pa[2][2];
        #pragma unroll
        for (int mt = 0; mt < 2; mt++) {
            int r0 = wbase + 16*mt + g;
            pa[mt][0] = P32[(r0    )*P_STRIDE + tg];
            pa[mt][1] = P32[(r0 + 8)*P_STRIDE + tg];
        }

        // ==== density pipeline, h fully register-resident ====
        // For each k16-tile ks: L1 MMA pair (jn=16ks, jn=16ks+8) produces the
        // EXACT m16n8k16 A-fragment {a0,a1,a2,a3}; feed straight into d0 MMA.
        float cd[2][2][8];   // [mt][nt][cA0..3, cB0..3]
        #pragma unroll
        for (int mt = 0; mt < 2; mt++)
            #pragma unroll
            for (int nt = 0; nt < 2; nt++)
                #pragma unroll
                for (int q = 0; q < 8; q++) cd[mt][nt][q] = 0.f;

        #pragma unroll
        for (int mt = 0; mt < 2; mt++) {
            #pragma unroll
            for (int ks = 0; ks < 8; ks++) {
                unsigned af0, af1, af2, af3;
                {
                    int jn = 16*ks;
                    unsigned b0 = WB1w[(jn + g)*WB1_STRIDE + tg];
                    float2 bj = *(const float2*)&sm[OFF_BD1 + jn + 2*tg];
                    float c0 = bj.x, c1 = bj.y, c2 = bj.x, c3 = bj.y;
                    mma_f16_k8(c0, c1, c2, c3, pa[mt][0], pa[mt][1], b0);
                    af0 = hmax2z(packh2(c0, c1));   // row g,   k 16ks+2tg..+1
                    af1 = hmax2z(packh2(c2, c3));   // row g+8
                }
                {
                    int jn = 16*ks + 8;
                    unsigned b0 = WB1w[(jn + g)*WB1_STRIDE + tg];
                    float2 bj = *(const float2*)&sm[OFF_BD1 + jn + 2*tg];
                    float c0 = bj.x, c1 = bj.y, c2 = bj.x, c3 = bj.y;
                    mma_f16_k8(c0, c1, c2, c3, pa[mt][0], pa[mt][1], b0);
                    af2 = hmax2z(packh2(c0, c1));   // row g,   k 16ks+8+2tg..+1
                    af3 = hmax2z(packh2(c2, c3));   // row g+8
                }
                int co = (ks & 1) ? 4 : 0;          // even ks -> cA, odd -> cB
                #pragma unroll
                for (int nt = 0; nt < 2; nt++) {
                    int coln = 8*nt + g;
                    float* c = cd[mt][nt] + co;
                    unsigned b00 = WD2w[(8*ks + tg    )*WD2_STRIDE + coln];
                    unsigned b01 = WD2w[(8*ks + tg + 4)*WD2_STRIDE + coln];
                    mma_f16(c[0], c[1], c[2], c[3], af0, af1, af2, af3, b00, b01);
                }
            }
        }

        // ---- store d0 frags into H words 0..15 of own rows ----
        #pragma unroll
        for (int mt = 0; mt < 2; mt++) {
            int r0 = wbase + 16*mt + g;
            #pragma unroll
            for (int nt = 0; nt < 2; nt++) {
                float* c = cd[mt][nt];
                int cb = 8*nt + 2*tg;
                float* rA = sm + OFF_H + (size_t)(r0    )*H_STRIDE + cb;
                float* rB = sm + OFF_H + (size_t)(r0 + 8)*H_STRIDE + cb;
                rA[0] = c[0] + c[4];  rA[1] = c[1] + c[5];
                rB[0] = c[2] + c[6];  rB[1] = c[3] + c[7];
            }
        }
        __syncwarp();

        // ---- readback d0 (own row), density out, build CIN in-place ----
        {
            float d0[16];
            const float4* drow = (const float4*)(sm + OFF_H + (size_t)tid*H_STRIDE);
            #pragma unroll
            for (int q = 0; q < 4; q++) {
                float4 v = drow[q];
                d0[4*q+0] = v.x + sm[OFF_BD2 + 4*q+0];
                d0[4*q+1] = v.y + sm[OFF_BD2 + 4*q+1];
                d0[4*q+2] = v.z + sm[OFF_BD2 + 4*q+2];
                d0[4*q+3] = v.w + sm[OFF_BD2 + 4*q+3];
            }
            if (valid) out[(size_t)4*p] = expf(d0[0]);

            float cv[56];
            cv[0] = dir[3*p]; cv[1] = dir[3*p+1]; cv[2] = dir[3*p+2];
            #pragma unroll
            for (int g2 = 0; g2 < GEO; g2++) cv[3+g2] = d0[1+g2];
            const float4* ap = (const float4*)(app + (size_t)p*APP);
            #pragma unroll
            for (int q = 0; q < APP/4; q++) {
                float4 v = __ldg(&ap[q]);
                cv[18+4*q+0] = v.x; cv[18+4*q+1] = v.y;
                cv[18+4*q+2] = v.z; cv[18+4*q+3] = v.w;
            }
            #pragma unroll
            for (int c = CIN; c < 56; c++) cv[c] = 0.f;
            #pragma unroll
            for (int q = 0; q < 8; q++) {     // words 0..31 (k padded to 64)
                uint4 v;
                v.x = (q < 7) ? packh2(cv[8*q+0], cv[8*q+1]) : 0u;
                v.y = (q < 7) ? packh2(cv[8*q+2], cv[8*q+3]) : 0u;
                v.z = (q < 7) ? packh2(cv[8*q+4], cv[8*q+5]) : 0u;
                v.w = (q < 7) ? packh2(cv[8*q+6], cv[8*q+7]) : 0u;
                hrow[q] = v;
            }
        }
        __syncwarp();

        // ---- color MMA (R10 verbatim): HC = relu(CIN@Wc1+bc1); RGB fused ----
        unsigned a[2][4][4];
        #pragma unroll
        for (int mt = 0; mt < 2; mt++) {
            int r0 = wbase + 16*mt + g;
            #pragma unroll
            for (int ks = 0; ks < 4; ks++) {
                int c = 8*ks + tg;
                a[mt][ks][0] = H32[(r0    )*H_STRIDE + c    ];
                a[mt][ks][1] = H32[(r0 + 8)*H_STRIDE + c    ];
                a[mt][ks][2] = H32[(r0    )*H_STRIDE + c + 4];
                a[mt][ks][3] = H32[(r0 + 8)*H_STRIDE + c + 4];
            }
        }

        float acc[4][3];
        #pragma unroll
        for (int q = 0; q < 4; q++) { acc[q][0]=0.f; acc[q][1]=0.f; acc[q][2]=0.f; }

        #pragma unroll 2
        for (int nb = 0; nb < 16; nb++) {
            int coln = 8*nb + g;
            unsigned b[4][2];
            #pragma unroll
            for (int ks = 0; ks < 4; ks++) {
                b[ks][0] = W32[(8*ks + tg    )*WC1_STRIDE + coln];
                b[ks][1] = W32[(8*ks + tg + 4)*WC1_STRIDE + coln];
            }
            int j0 = 8*nb + 2*tg;
            float bj0 = sm[OFF_BC1 + j0], bj1 = sm[OFF_BC1 + j0 + 1];
            float4 w0 = WC2v[j0];
            float4 w1 = WC2v[j0 + 1];

            #pragma unroll
            for (int mt = 0; mt < 2; mt++) {
                float cA0=0.f,cA1=0.f,cA2=0.f,cA3=0.f;
                float cB0=0.f,cB1=0.f,cB2=0.f,cB3=0.f;
                mma_f16(cA0,cA1,cA2,cA3, a[mt][0][0],a[mt][0][1],a[mt][0][2],a[mt][0][3], b[0][0],b[0][1]);
                mma_f16(cB0,cB1,cB2,cB3, a[mt][1][0],a[mt][1][1],a[mt][1][2],a[mt][1][3], b[1][0],b[1][1]);
                mma_f16(cA0,cA1,cA2,cA3, a[mt][2][0],a[mt][2][1],a[mt][2][2],a[mt][2][3], b[2][0],b[2][1]);
                mma_f16(cB0,cB1,cB2,cB3, a[mt][3][0],a[mt][3][1],a[mt][3][2],a[mt][3][3], b[3][0],b[3][1]);
                float h00 = fmaxf(cA0 + cB0 + bj0, 0.f);
                float h01 = fmaxf(cA1 + cB1 + bj1, 0.f);
                float h10 = fmaxf(cA2 + cB2 + bj0, 0.f);
                float h11 = fmaxf(cA3 + cB3 + bj1, 0.f);
                int q0 = 2*mt, q1 = 2*mt + 1;
                acc[q0][0] = fmaf(h00, w0.x, fmaf(h01, w1.x, acc[q0][0]));
                acc[q0][1] = fmaf(h00, w0.y, fmaf(h01, w1.y, acc[q0][1]));
                acc[q0][2] = fmaf(h00, w0.z, fmaf(h01, w1.z, acc[q0][2]));
                acc[q1][0] = fmaf(h10, w0.x, fmaf(h11, w1.x, acc[q1][0]));
                acc[q1][1] = fmaf(h10, w0.y, fmaf(h11, w1.y, acc[q1][1]));
                acc[q1][2] = fmaf(h10, w0.z, fmaf(h11, w1.z, acc[q1][2]));
            }
        }

        #pragma unroll
        for (int q = 0; q < 4; q++)
            #pragma unroll
            for (int c = 0; c < 3; c++) {
                float v = acc[q][c];
                v += __shfl_xor_sync(0xffffffffu, v, 1);
                v += __shfl_xor_sync(0xffffffffu, v, 2);
                acc[q][c] = v;
            }

        {
            int row = wbase + g + 8*tg;
            int bi2 = base + row;
            if (bi2 < cnt) {
                int pp = g_bucket[f][bi2];
                float r0 = acc[tg][0] + sm[OFF_BC2 + 0];
                float r1 = acc[tg][1] + sm[OFF_BC2 + 1];
                float r2 = acc[tg][2] + sm[OFF_BC2 + 2];
                out[(size_t)4*pp + 1] = 1.f / (1.f + expf(-r0));
                out[(size_t)4*pp + 2] = 1.f / (1.f + expf(-r1));
                out[(size_t)4*pp + 3] = 1.f / (1.f + expf(-r2));
            }
        }
        __syncwarp();   // protect H/P reuse next tile
    }
}

// ---------------- launch ----------------
extern "C" void kernel_launch(void* const* d_in, const int* in_sizes, int n_in,
                              void* d_out, int out_size) {
    const float* positions  = (const float*)d_in[0];
    const float* directions = (const float*)d_in[1];
    const float* appearance = (const float*)d_in[2];
    const float* centroids  = (const float*)d_in[3];
    const float* Wd1 = (const float*)d_in[4];
    const float* bd1 = (const float*)d_in[5];
    const float* Wd2 = (const float*)d_in[6];
    const float* bd2 = (const float*)d_in[7];
    const float* Wc1 = (const float*)d_in[8];
    const float* bc1 = (const float*)d_in[9];
    const float* Wc2 = (const float*)d_in[10];
    const float* bc2 = (const float*)d_in[11];
    float* out = (float*)d_out;

    int n = in_sizes[0] / 3;
    if (n > N_MAX) n = N_MAX;
    int tpf = (n + PTS_PER_BLOCK - 1) / PTS_PER_BLOCK;

    cudaFuncSetAttribute(k_field, cudaFuncAttributeMaxDynamicSharedMemorySize,
                         SMEM_BYTES);

    void* cptr = nullptr;
    cudaGetSymbolAddress(&cptr, g_counts);
    cudaMemsetAsync(cptr, 0, N_FIELDS * sizeof(int));

    k_assign<<<(n + 255) / 256, 256>>>(positions, centroids, n);
    k_field<<<N_FIELDS * tpf, TILE, SMEM_BYTES>>>(positions, directions, appearance,
                                                  Wd1, bd1, Wd2, bd2, Wc1, bc1,
                                                  Wc2, bc2, out, tpf);
}

// round 15
// speedup vs baseline: 1.6056x; 1.0260x over previous
#include <cuda_runtime.h>
#include <cuda_fp16.h>
#include <math.h>

#define N_FIELDS 8
#define HIDDEN   128
#define GEO      15
#define APP      32
#define CIN      50
#define N_MAX    524288
#define TILE     128
#define TILES_PER_BLOCK 8
#define PTS_PER_BLOCK   1024

#define H_STRIDE   36    // words/row; CIN + d0 scratch
#define WD2_STRIDE 24    // k-major [kp=64][n=16]
#define WC1_STRIDE 136   // 136%32=8 -> conflict-free
#define P_STRIDE   4     // pos tile [128][4] half2 words
#define WB1_STRIDE 4     // Wd1 n-major [128][4] half2 words
#define WC2_STRIDE 8     // Wc2 half2 [kp=64][n=8]; bank 8tg+g conflict-free

// ---- dynamic smem layout (32-bit word offsets) ----
#define OFF_BD1    0       // 128
#define OFF_BD2    128     // 16
#define OFF_BC1    144     // 128
#define OFF_BC2    272     // 4
#define OFF_WC2    276     // [64][8] = 512 half2 words
#define OFF_WD2H   788     // [64][24] = 1536
#define OFF_WC1    2324    // [32][136] = 4352
#define OFF_P      6676    // [128][4] = 512
#define OFF_WB1    7188    // [128][4] = 512
#define OFF_H      7700    // [128][36] = 4608 ; byte 30800, 16B aligned
#define SMEM_WORDS 12308
#define SMEM_BYTES (SMEM_WORDS * 4)   // 49232 B -> 4 blocks/SM

// ---------------- device scratch ----------------
__device__ int g_counts[N_FIELDS];
__device__ int g_bucket[N_FIELDS][N_MAX];

__global__ void k_assign(const float* __restrict__ pos,
                         const float* __restrict__ cent, int n) {
    int i = blockIdx.x * blockDim.x + threadIdx.x;
    unsigned act = __ballot_sync(0xffffffffu, i < n);
    if (i >= n) return;
    float px = pos[3*i], py = pos[3*i+1], pz = pos[3*i+2];
    int best = 0; float bd = 3.402823e38f;
    #pragma unroll
    for (int c = 0; c < N_FIELDS; c++) {
        float dx = px - __ldg(&cent[3*c+0]);
        float dy = py - __ldg(&cent[3*c+1]);
        float dz = pz - __ldg(&cent[3*c+2]);
        float d = dx*dx + dy*dy + dz*dz;
        if (d < bd) { bd = d; best = c; }
    }
    unsigned peers  = __match_any_sync(act, best);
    int leader = __ffs(peers) - 1;
    int lane   = threadIdx.x & 31;
    int base = 0;
    if (lane == leader) base = atomicAdd(&g_counts[best], __popc(peers));
    base = __shfl_sync(peers, base, leader);
    g_bucket[best][base + __popc(peers & ((1u << lane) - 1u))] = i;
}

// ---- helpers ----
__device__ __forceinline__ unsigned packh2(float lo, float hi) {
    __half2 h = __floats2half2_rn(lo, hi);
    return *(unsigned*)&h;
}
__device__ __forceinline__ unsigned hmax2z(unsigned w) {
    __half2 h = *(__half2*)&w;
    h = __hmax2(h, __float2half2_rn(0.f));
    return *(unsigned*)&h;
}
__device__ __forceinline__ void mma_f16(float& c0, float& c1, float& c2, float& c3,
                                        unsigned a0, unsigned a1, unsigned a2, unsigned a3,
                                        unsigned b0, unsigned b1) {
    asm("mma.sync.aligned.m16n8k16.row.col.f32.f16.f16.f32 "
        "{%0,%1,%2,%3},{%4,%5,%6,%7},{%8,%9},{%0,%1,%2,%3};"
        : "+f"(c0), "+f"(c1), "+f"(c2), "+f"(c3)
        : "r"(a0), "r"(a1), "r"(a2), "r"(a3), "r"(b0), "r"(b1));
}
__device__ __forceinline__ void mma_f16_k8(float& c0, float& c1, float& c2, float& c3,
                                           unsigned a0, unsigned a1, unsigned b0) {
    asm("mma.sync.aligned.m16n8k8.row.col.f32.f16.f16.f32 "
        "{%0,%1,%2,%3},{%4,%5},{%6},{%0,%1,%2,%3};"
        : "+f"(c0), "+f"(c1), "+f"(c2), "+f"(c3)
        : "r"(a0), "r"(a1), "r"(b0));
}
__device__ __forceinline__ float sigm(float x) {
    return 1.f / (1.f + expf(-x));
}

// ---------------- kernel 2 ----------------
__global__ void __launch_bounds__(TILE, 4)
k_field(const float* __restrict__ pos, const float* __restrict__ dir,
        const float* __restrict__ app,
        const float* __restrict__ Wd1, const float* __restrict__ bd1,
        const float* __restrict__ Wd2, const float* __restrict__ bd2,
        const float* __restrict__ Wc1, const float* __restrict__ bc1,
        const float* __restrict__ Wc2, const float* __restrict__ bc2,
        float* __restrict__ out, int tpf)
{
    extern __shared__ float sm[];
    unsigned* smw = (unsigned*)sm;

    int f = blockIdx.x / tpf;
    int t = blockIdx.x - f * tpf;
    int cnt = g_counts[f];
    if (t * PTS_PER_BLOCK >= cnt) return;

    int tid = threadIdx.x;

    // ---- stage weights (once per block) ----
    sm[OFF_BD1 + tid] = bd1[f*HIDDEN + tid];
    if (tid < 16) sm[OFF_BD2 + tid] = bd2[f*16 + tid];
    sm[OFF_BC1 + tid] = bc1[f*HIDDEN + tid];
    if (tid < 3) sm[OFF_BC2 + tid] = bc2[f*3 + tid];
    if (tid == 3) sm[OFF_BC2 + 3] = 0.f;
    {   // Wd1 [3][128] -> n-major half2 [n=128][4]
        const float* g = Wd1 + f*3*HIDDEN;
        smw[OFF_WB1 + tid*WB1_STRIDE + 0] = packh2(g[0*HIDDEN + tid], g[1*HIDDEN + tid]);
        smw[OFF_WB1 + tid*WB1_STRIDE + 1] = packh2(g[2*HIDDEN + tid], 0.f);
        smw[OFF_WB1 + tid*WB1_STRIDE + 2] = 0u;
        smw[OFF_WB1 + tid*WB1_STRIDE + 3] = 0u;
        smw[OFF_P + tid*P_STRIDE + 2] = 0u;
        smw[OFF_P + tid*P_STRIDE + 3] = 0u;
    }
    {   // Wd2 [k=128][n=16] -> half2 [kp=64][n=16], stride 24
        const float* g = Wd2 + f*HIDDEN*16;
        for (int i = tid; i < 64*16; i += TILE) {
            int kp = i >> 4, nn = i & 15;
            smw[OFF_WD2H + kp*WD2_STRIDE + nn] =
                packh2(g[(2*kp)*16 + nn], g[(2*kp+1)*16 + nn]);
        }
    }
    {   // Wc1 [k=50][n=128] -> half2 [kp=32][n=128], stride 136
        const float* g = Wc1 + f*CIN*HIDDEN;
        for (int i = tid; i < 32*HIDDEN; i += TILE) {
            int kp = i >> 7, nn = i & 127;
            unsigned w = 0u;
            if (kp < 25)
                w = packh2(g[(2*kp)*HIDDEN + nn], g[(2*kp+1)*HIDDEN + nn]);
            smw[OFF_WC1 + kp*WC1_STRIDE + nn] = w;
        }
    }
    {   // Wc2 [k=128][n=3] -> half2 [kp=64][n=8] (n 3..7 zero)
        const float* g = Wc2 + f*HIDDEN*3;
        for (int i = tid; i < 64*8; i += TILE) {
            int kp = i >> 3, nn = i & 7;
            unsigned w = 0u;
            if (nn < 3)
                w = packh2(g[(2*kp)*3 + nn], g[(2*kp+1)*3 + nn]);
            smw[OFF_WC2 + kp*WC2_STRIDE + nn] = w;
        }
    }
    __syncthreads();

    int lane = tid & 31;
    int wid  = tid >> 5;
    int g    = lane >> 2;
    int tg   = lane & 3;
    int wbase = wid * 32;

    const unsigned* H32  = smw + OFF_H;
    const unsigned* WD2w = smw + OFF_WD2H;
    const unsigned* W32  = smw + OFF_WC1;
    const unsigned* P32  = smw + OFF_P;
    const unsigned* WB1w = smw + OFF_WB1;
    const unsigned* WC2w = smw + OFF_WC2;

    for (int tile = 0; tile < TILES_PER_BLOCK; tile++) {
        int base = t * PTS_PER_BLOCK + tile * TILE;
        if (base >= cnt) break;
        int bi = base + tid;
        bool valid = (bi < cnt);
        int p = g_bucket[f][valid ? bi : (cnt - 1)];

        float px = pos[3*p], py = pos[3*p+1], pz = pos[3*p+2];
        uint4* hrow = (uint4*)(smw + OFF_H + tid*H_STRIDE);

        // ---- stage this tile's pos rows ----
        smw[OFF_P + tid*P_STRIDE + 0] = packh2(px, py);
        smw[OFF_P + tid*P_STRIDE + 1] = packh2(pz, 0.f);
        __syncwarp();

        unsigned pa[2][2];
        #pragma unroll
        for (int mt = 0; mt < 2; mt++) {
            int r0 = wbase + 16*mt + g;
            pa[mt][0] = P32[(r0    )*P_STRIDE + tg];
            pa[mt][1] = P32[(r0 + 8)*P_STRIDE + tg];
        }

        // ==== density pipeline, h fully register-resident (R14) ====
        float cd[2][2][8];
        #pragma unroll
        for (int mt = 0; mt < 2; mt++)
            #pragma unroll
            for (int nt = 0; nt < 2; nt++)
                #pragma unroll
                for (int q = 0; q < 8; q++) cd[mt][nt][q] = 0.f;

        #pragma unroll
        for (int mt = 0; mt < 2; mt++) {
            #pragma unroll
            for (int ks = 0; ks < 8; ks++) {
                unsigned af0, af1, af2, af3;
                {
                    int jn = 16*ks;
                    unsigned b0 = WB1w[(jn + g)*WB1_STRIDE + tg];
                    float2 bj = *(const float2*)&sm[OFF_BD1 + jn + 2*tg];
                    float c0 = bj.x, c1 = bj.y, c2 = bj.x, c3 = bj.y;
                    mma_f16_k8(c0, c1, c2, c3, pa[mt][0], pa[mt][1], b0);
                    af0 = hmax2z(packh2(c0, c1));
                    af1 = hmax2z(packh2(c2, c3));
                }
                {
                    int jn = 16*ks + 8;
                    unsigned b0 = WB1w[(jn + g)*WB1_STRIDE + tg];
                    float2 bj = *(const float2*)&sm[OFF_BD1 + jn + 2*tg];
                    float c0 = bj.x, c1 = bj.y, c2 = bj.x, c3 = bj.y;
                    mma_f16_k8(c0, c1, c2, c3, pa[mt][0], pa[mt][1], b0);
                    af2 = hmax2z(packh2(c0, c1));
                    af3 = hmax2z(packh2(c2, c3));
                }
                int co = (ks & 1) ? 4 : 0;
                #pragma unroll
                for (int nt = 0; nt < 2; nt++) {
                    int coln = 8*nt + g;
                    float* c = cd[mt][nt] + co;
                    unsigned b00 = WD2w[(8*ks + tg    )*WD2_STRIDE + coln];
                    unsigned b01 = WD2w[(8*ks + tg + 4)*WD2_STRIDE + coln];
                    mma_f16(c[0], c[1], c[2], c[3], af0, af1, af2, af3, b00, b01);
                }
            }
        }

        // ---- store d0 frags into H words 0..15 of own rows ----
        #pragma unroll
        for (int mt = 0; mt < 2; mt++) {
            int r0 = wbase + 16*mt + g;
            #pragma unroll
            for (int nt = 0; nt < 2; nt++) {
                float* c = cd[mt][nt];
                int cb = 8*nt + 2*tg;
                float* rA = sm + OFF_H + (size_t)(r0    )*H_STRIDE + cb;
                float* rB = sm + OFF_H + (size_t)(r0 + 8)*H_STRIDE + cb;
                rA[0] = c[0] + c[4];  rA[1] = c[1] + c[5];
                rB[0] = c[2] + c[6];  rB[1] = c[3] + c[7];
            }
        }
        __syncwarp();

        // ---- readback d0 (own row), density out, build CIN in-place ----
        {
            float d0[16];
            const float4* drow = (const float4*)(sm + OFF_H + (size_t)tid*H_STRIDE);
            #pragma unroll
            for (int q = 0; q < 4; q++) {
                float4 v = drow[q];
                d0[4*q+0] = v.x + sm[OFF_BD2 + 4*q+0];
                d0[4*q+1] = v.y + sm[OFF_BD2 + 4*q+1];
                d0[4*q+2] = v.z + sm[OFF_BD2 + 4*q+2];
                d0[4*q+3] = v.w + sm[OFF_BD2 + 4*q+3];
            }
            if (valid) out[(size_t)4*p] = expf(d0[0]);

            float cv[56];
            cv[0] = dir[3*p]; cv[1] = dir[3*p+1]; cv[2] = dir[3*p+2];
            #pragma unroll
            for (int g2 = 0; g2 < GEO; g2++) cv[3+g2] = d0[1+g2];
            const float4* ap = (const float4*)(app + (size_t)p*APP);
            #pragma unroll
            for (int q = 0; q < APP/4; q++) {
                float4 v = __ldg(&ap[q]);
                cv[18+4*q+0] = v.x; cv[18+4*q+1] = v.y;
                cv[18+4*q+2] = v.z; cv[18+4*q+3] = v.w;
            }
            #pragma unroll
            for (int c = CIN; c < 56; c++) cv[c] = 0.f;
            #pragma unroll
            for (int q = 0; q < 8; q++) {
                uint4 v;
                v.x = (q < 7) ? packh2(cv[8*q+0], cv[8*q+1]) : 0u;
                v.y = (q < 7) ? packh2(cv[8*q+2], cv[8*q+3]) : 0u;
                v.z = (q < 7) ? packh2(cv[8*q+4], cv[8*q+5]) : 0u;
                v.w = (q < 7) ? packh2(cv[8*q+6], cv[8*q+7]) : 0u;
                hrow[q] = v;
            }
        }
        __syncwarp();

        // ---- color MMA + rgb via chained MMA ----
        unsigned a[2][4][4];
        #pragma unroll
        for (int mt = 0; mt < 2; mt++) {
            int r0 = wbase + 16*mt + g;
            #pragma unroll
            for (int ks = 0; ks < 4; ks++) {
                int c = 8*ks + tg;
                a[mt][ks][0] = H32[(r0    )*H_STRIDE + c    ];
                a[mt][ks][1] = H32[(r0 + 8)*H_STRIDE + c    ];
                a[mt][ks][2] = H32[(r0    )*H_STRIDE + c + 4];
                a[mt][ks][3] = H32[(r0 + 8)*H_STRIDE + c + 4];
            }
        }

        float racc[2][4];      // rgb C-frags per mt
        #pragma unroll
        for (int mt = 0; mt < 2; mt++)
            #pragma unroll
            for (int q = 0; q < 4; q++) racc[mt][q] = 0.f;
        unsigned afr[2][2];    // pending hc A-frag halves (from even nb)

        #pragma unroll 2
        for (int nb = 0; nb < 16; nb++) {
            int coln = 8*nb + g;
            unsigned b[4][2];
            #pragma unroll
            for (int ks = 0; ks < 4; ks++) {
                b[ks][0] = W32[(8*ks + tg    )*WC1_STRIDE + coln];
                b[ks][1] = W32[(8*ks + tg + 4)*WC1_STRIDE + coln];
            }
            int j0 = 8*nb + 2*tg;
            float bj0 = sm[OFF_BC1 + j0], bj1 = sm[OFF_BC1 + j0 + 1];

            #pragma unroll
            for (int mt = 0; mt < 2; mt++) {
                float cA0=0.f,cA1=0.f,cA2=0.f,cA3=0.f;
                float cB0=0.f,cB1=0.f,cB2=0.f,cB3=0.f;
                mma_f16(cA0,cA1,cA2,cA3, a[mt][0][0],a[mt][0][1],a[mt][0][2],a[mt][0][3], b[0][0],b[0][1]);
                mma_f16(cB0,cB1,cB2,cB3, a[mt][1][0],a[mt][1][1],a[mt][1][2],a[mt][1][3], b[1][0],b[1][1]);
                mma_f16(cA0,cA1,cA2,cA3, a[mt][2][0],a[mt][2][1],a[mt][2][2],a[mt][2][3], b[2][0],b[2][1]);
                mma_f16(cB0,cB1,cB2,cB3, a[mt][3][0],a[mt][3][1],a[mt][3][2],a[mt][3][3], b[3][0],b[3][1]);
                float h00 = fmaxf(cA0 + cB0 + bj0, 0.f);
                float h01 = fmaxf(cA1 + cB1 + bj1, 0.f);
                float h10 = fmaxf(cA2 + cB2 + bj0, 0.f);
                float h11 = fmaxf(cA3 + cB3 + bj1, 0.f);
                unsigned u0 = packh2(h00, h01);
                unsigned u1 = packh2(h10, h11);
                if ((nb & 1) == 0) {
                    afr[mt][0] = u0;  afr[mt][1] = u1;
                } else {
                    int s = nb >> 1;   // rgb k-tile
                    unsigned wb0 = WC2w[(8*s + tg    )*WC2_STRIDE + g];
                    unsigned wb1 = WC2w[(8*s + tg + 4)*WC2_STRIDE + g];
                    mma_f16(racc[mt][0], racc[mt][1], racc[mt][2], racc[mt][3],
                            afr[mt][0], afr[mt][1], u0, u1, wb0, wb1);
                }
            }
        }

        // ---- rgb writeout: C-frag cols n=2tg,2tg+1; rows g / g+8 per mt ----
        if (tg < 2) {
            #pragma unroll
            for (int mt = 0; mt < 2; mt++) {
                int r0 = wbase + 16*mt + g;
                #pragma unroll
                for (int half = 0; half < 2; half++) {
                    int row = r0 + 8*half;
                    int bi2 = base + row;
                    if (bi2 < cnt) {
                        int pp = g_bucket[f][bi2];
                        float v0 = racc[mt][2*half + 0];
                        float v1 = racc[mt][2*half + 1];
                        if (tg == 0) {
                            out[(size_t)4*pp + 1] = sigm(v0 + sm[OFF_BC2 + 0]);
                            out[(size_t)4*pp + 2] = sigm(v1 + sm[OFF_BC2 + 1]);
                        } else {
                            out[(size_t)4*pp + 3] = sigm(v0 + sm[OFF_BC2 + 2]);
                        }
                    }
                }
            }
        }
        __syncwarp();   // protect H/P reuse next tile
    }
}

// ---------------- launch ----------------
extern "C" void kernel_launch(void* const* d_in, const int* in_sizes, int n_in,
                              void* d_out, int out_size) {
    const float* positions  = (const float*)d_in[0];
    const float* directions = (const float*)d_in[1];
    const float* appearance = (const float*)d_in[2];
    const float* centroids  = (const float*)d_in[3];
    const float* Wd1 = (const float*)d_in[4];
    const float* bd1 = (const float*)d_in[5];
    const float* Wd2 = (const float*)d_in[6];
    const float* bd2 = (const float*)d_in[7];
    const float* Wc1 = (const float*)d_in[8];
    const float* bc1 = (const float*)d_in[9];
    const float* Wc2 = (const float*)d_in[10];
    const float* bc2 = (const float*)d_in[11];
    float* out = (float*)d_out;

    int n = in_sizes[0] / 3;
    if (n > N_MAX) n = N_MAX;
    int tpf = (n + PTS_PER_BLOCK - 1) / PTS_PER_BLOCK;

    cudaFuncSetAttribute(k_field, cudaFuncAttributeMaxDynamicSharedMemorySize,
                         SMEM_BYTES);

    void* cptr = nullptr;
    cudaGetSymbolAddress(&cptr, g_counts);
    cudaMemsetAsync(cptr, 0, N_FIELDS * sizeof(int));

    k_assign<<<(n + 255) / 256, 256>>>(positions, centroids, n);
    k_field<<<N_FIELDS * tpf, TILE, SMEM_BYTES>>>(positions, directions, appearance,
                                                  Wd1, bd1, Wd2, bd2, Wc1, bc1,
                                                  Wc2, bc2, out, tpf);
}